// round 11
// baseline (speedup 1.0000x reference)
#include <cuda_runtime.h>

#define NN 50000
#define NE 800000
#define NG 128
#define DIN 96

// ---- scratch (__device__ globals; no allocs allowed) ----
// g_big serves two non-overlapping lifetimes:
//   phase A (launches 4-7): mean-aggregate buffer [NN*96]
//   phase B (launches 8-9): pq projection buffer  [NN*128]
__device__ float g_big[NN * 128];
__device__ float g_ha[NN * DIN];
__device__ float g_hb[NN * DIN];
__device__ int   g_cnt[NN];      // INVARIANT: zero at kernel_launch entry (scanall re-zeroes)
__device__ int   g_rowptr[NN + 1];
__device__ int   g_wp[NN];
__device__ int   g_esrc[NE];

static inline int cdiv(int a, int b) { return (a + b - 1) / b; }

// ---- f32x2 helpers (FFMA2 only reachable via PTX) ----
typedef unsigned long long u64;
__device__ __forceinline__ u64 pk(float lo, float hi) {
    u64 r; asm("mov.b64 %0,{%1,%2};" : "=l"(r) : "f"(lo), "f"(hi)); return r;
}
__device__ __forceinline__ float2 upk(u64 v) {
    float2 f; asm("mov.b64 {%0,%1},%2;" : "=f"(f.x), "=f"(f.y) : "l"(v)); return f;
}
__device__ __forceinline__ void fma2(u64& d, u64 a, u64 b) {
    asm("fma.rn.f32x2 %0,%1,%2,%0;" : "+l"(d) : "l"(a), "l"(b));
}

// ================= CSR build =================
__global__ void hist_kernel(const int* __restrict__ dst) {
    int i = blockIdx.x * blockDim.x + threadIdx.x;
    if (i < NE) atomicAdd(&g_cnt[dst[i]], 1);
}

// One block, 1024 threads, 49 elems/thread: exclusive scan of g_cnt -> rowptr/wp.
// Re-zeroes g_cnt to maintain the entry invariant.
__global__ void __launch_bounds__(1024) scanall_kernel() {
    __shared__ int tot[1024];
    const int C = 49;  // 49*1024 >= NN
    int t = threadIdx.x;
    int base = t * C;
    int s = 0;
    for (int u = 0; u < C; u++) {
        int i = base + u;
        if (i < NN) s += g_cnt[i];
    }
    tot[t] = s;
    __syncthreads();
    for (int off = 1; off < 1024; off <<= 1) {
        int v = (t >= off) ? tot[t - off] : 0;
        __syncthreads();
        tot[t] += v;
        __syncthreads();
    }
    int pre = tot[t] - s;
    for (int u = 0; u < C; u++) {
        int i = base + u;
        if (i < NN) {
            int c = g_cnt[i];
            g_rowptr[i] = pre;
            g_wp[i] = pre;
            pre += c;
            g_cnt[i] = 0;
        }
    }
    if (t == 1023) g_rowptr[NN] = NE;
}

__global__ void fill_kernel(const int* __restrict__ src, const int* __restrict__ dst) {
    int i = blockIdx.x * blockDim.x + threadIdx.x;
    if (i < NE) {
        int s = __ldg(&src[i]);
        int pos = atomicAdd(&g_wp[dst[i]], 1);
        g_esrc[pos] = s;
    }
}

// ========== mean aggregation (96-wide): warp/node, 8-deep pipeline ==========
__global__ void __launch_bounds__(256) gather_kernel(const float* __restrict__ x) {
    int node = (blockIdx.x * blockDim.x + threadIdx.x) >> 5;
    int lane = threadIdx.x & 31;
    if (node >= NN) return;
    int beg = g_rowptr[node], end = g_rowptr[node + 1];

    float4 acc = make_float4(0.f, 0.f, 0.f, 0.f);
    const float4* __restrict__ x4 = (const float4*)x;   // row = 24 float4
    bool act = lane < 24;

    for (int base = beg; base < end; base += 32) {
        int cnt = end - base;
        if (cnt > 32) cnt = 32;
        int myidx = g_esrc[base + (lane < cnt ? lane : 0)];
        int j = 0;
        for (; j + 8 <= cnt; j += 8) {
            int s0 = __shfl_sync(0xffffffffu, myidx, j);
            int s1 = __shfl_sync(0xffffffffu, myidx, j + 1);
            int s2 = __shfl_sync(0xffffffffu, myidx, j + 2);
            int s3 = __shfl_sync(0xffffffffu, myidx, j + 3);
            int s4 = __shfl_sync(0xffffffffu, myidx, j + 4);
            int s5 = __shfl_sync(0xffffffffu, myidx, j + 5);
            int s6 = __shfl_sync(0xffffffffu, myidx, j + 6);
            int s7 = __shfl_sync(0xffffffffu, myidx, j + 7);
            if (act) {
                float4 v0 = __ldg(&x4[(size_t)s0 * 24 + lane]);
                float4 v1 = __ldg(&x4[(size_t)s1 * 24 + lane]);
                float4 v2 = __ldg(&x4[(size_t)s2 * 24 + lane]);
                float4 v3 = __ldg(&x4[(size_t)s3 * 24 + lane]);
                float4 v4 = __ldg(&x4[(size_t)s4 * 24 + lane]);
                float4 v5 = __ldg(&x4[(size_t)s5 * 24 + lane]);
                float4 v6 = __ldg(&x4[(size_t)s6 * 24 + lane]);
                float4 v7 = __ldg(&x4[(size_t)s7 * 24 + lane]);
                acc.x += (v0.x + v1.x) + (v2.x + v3.x) + ((v4.x + v5.x) + (v6.x + v7.x));
                acc.y += (v0.y + v1.y) + (v2.y + v3.y) + ((v4.y + v5.y) + (v6.y + v7.y));
                acc.z += (v0.z + v1.z) + (v2.z + v3.z) + ((v4.z + v5.z) + (v6.z + v7.z));
                acc.w += (v0.w + v1.w) + (v2.w + v3.w) + ((v4.w + v5.w) + (v6.w + v7.w));
            }
        }
        for (; j < cnt; j++) {
            int s0 = __shfl_sync(0xffffffffu, myidx, j);
            if (act) {
                float4 v0 = __ldg(&x4[(size_t)s0 * 24 + lane]);
                acc.x += v0.x; acc.y += v0.y; acc.z += v0.z; acc.w += v0.w;
            }
        }
    }
    if (act) {
        float inv = 1.0f / fmaxf((float)(end - beg), 1.0f);
        acc.x *= inv; acc.y *= inv; acc.z *= inv; acc.w *= inv;
        ((float4*)(g_big + (size_t)node * DIN))[lane] = acc;
    }
}

// ===== layer-2 gather: mean over p (cols 0..63 of pq) + q (cols 64..127) -> ha[N,64]
__global__ void __launch_bounds__(256) gather_pq_kernel() {
    int node = (blockIdx.x * blockDim.x + threadIdx.x) >> 5;
    int lane = threadIdx.x & 31;
    if (node >= NN) return;
    int beg = g_rowptr[node], end = g_rowptr[node + 1];

    const float2* __restrict__ pq2 = (const float2*)g_big;  // row = 64 float2
    float2 q = __ldg(&pq2[(size_t)node * 64 + 32 + lane]);  // overlap with gather loop
    float2 acc = make_float2(0.f, 0.f);

    for (int base = beg; base < end; base += 32) {
        int cnt = end - base;
        if (cnt > 32) cnt = 32;
        int myidx = g_esrc[base + (lane < cnt ? lane : 0)];
        int j = 0;
        for (; j + 8 <= cnt; j += 8) {
            int s0 = __shfl_sync(0xffffffffu, myidx, j);
            int s1 = __shfl_sync(0xffffffffu, myidx, j + 1);
            int s2 = __shfl_sync(0xffffffffu, myidx, j + 2);
            int s3 = __shfl_sync(0xffffffffu, myidx, j + 3);
            int s4 = __shfl_sync(0xffffffffu, myidx, j + 4);
            int s5 = __shfl_sync(0xffffffffu, myidx, j + 5);
            int s6 = __shfl_sync(0xffffffffu, myidx, j + 6);
            int s7 = __shfl_sync(0xffffffffu, myidx, j + 7);
            float2 v0 = __ldg(&pq2[(size_t)s0 * 64 + lane]);
            float2 v1 = __ldg(&pq2[(size_t)s1 * 64 + lane]);
            float2 v2 = __ldg(&pq2[(size_t)s2 * 64 + lane]);
            float2 v3 = __ldg(&pq2[(size_t)s3 * 64 + lane]);
            float2 v4 = __ldg(&pq2[(size_t)s4 * 64 + lane]);
            float2 v5 = __ldg(&pq2[(size_t)s5 * 64 + lane]);
            float2 v6 = __ldg(&pq2[(size_t)s6 * 64 + lane]);
            float2 v7 = __ldg(&pq2[(size_t)s7 * 64 + lane]);
            acc.x += (v0.x + v1.x) + (v2.x + v3.x) + ((v4.x + v5.x) + (v6.x + v7.x));
            acc.y += (v0.y + v1.y) + (v2.y + v3.y) + ((v4.y + v5.y) + (v6.y + v7.y));
        }
        for (; j < cnt; j++) {
            int s0 = __shfl_sync(0xffffffffu, myidx, j);
            float2 v0 = __ldg(&pq2[(size_t)s0 * 64 + lane]);
            acc.x += v0.x; acc.y += v0.y;
        }
    }
    float inv = 1.0f / fmaxf((float)(end - beg), 1.0f);
    float2 r = make_float2(acc.x * inv + q.x, acc.y * inv + q.y);
    ((float2*)(g_ha + (size_t)node * 64))[lane] = r;
}

// ================= dual-input SAGE GEMM (layers 0,1; f32x2, pre-dup A) ============
template<int DOUT>
__global__ void __launch_bounds__(256)
sage_gemm(const float* __restrict__ xin,
          const float* __restrict__ mean,
          const float* __restrict__ Wl,
          const float* __restrict__ bias,
          const float* __restrict__ Wr,
          float* __restrict__ out) {
    constexpr int WP  = DOUT + 2;
    constexpr int NJP = DOUT / 32;
    constexpr int AP  = 4 * DIN + 4;  // 388
    extern __shared__ float sm[];
    float* Wlt = sm;
    float* Wrt = Wlt + DIN * WP;
    float* bs  = Wrt + DIN * WP;
    float* A   = bs + DOUT;

    int tid = threadIdx.x;
    for (int idx = tid; idx < DOUT * DIN; idx += 256) {
        int j = idx / DIN, k = idx - j * DIN;
        Wlt[k * WP + j] = Wl[idx];
        Wrt[k * WP + j] = Wr[idx];
    }
    if (tid < DOUT) bs[tid] = bias[tid];

    int node0 = blockIdx.x * 64;
    for (int idx = tid; idx < 64 * DIN; idx += 256) {
        int n = idx / DIN, k = idx - n * DIN;
        int node = node0 + n;
        float m = 0.f, xv = 0.f;
        if (node < NN) {
            m  = mean[(size_t)node * DIN + k];
            xv = xin[(size_t)node * DIN + k];
        }
        *(float2*)&A[n * AP + 4 * k]     = make_float2(m, m);
        *(float2*)&A[n * AP + 4 * k + 2] = make_float2(xv, xv);
    }
    __syncthreads();

    int tx = tid & 15, ty = tid >> 4;
    u64 acc[4][NJP];
#pragma unroll
    for (int jj = 0; jj < NJP; jj++) {
        float2 bp = *(const float2*)&bs[2 * tx + 32 * jj];
        u64 bv = pk(bp.x, bp.y);
#pragma unroll
        for (int nn = 0; nn < 4; nn++) acc[nn][jj] = bv;
    }

#pragma unroll 2
    for (int k = 0; k < DIN; k++) {
        u64 am2[4], ax2[4];
#pragma unroll
        for (int nn = 0; nn < 4; nn++) {
            const float* ap = &A[(nn * 16 + ty) * AP + 4 * k];
            am2[nn] = *(const u64*)(ap);
            ax2[nn] = *(const u64*)(ap + 2);
        }
#pragma unroll
        for (int jj = 0; jj < NJP; jj++) {
            u64 wl2 = *(const u64*)&Wlt[k * WP + 2 * tx + 32 * jj];
            u64 wr2 = *(const u64*)&Wrt[k * WP + 2 * tx + 32 * jj];
#pragma unroll
            for (int nn = 0; nn < 4; nn++) {
                fma2(acc[nn][jj], am2[nn], wl2);
                fma2(acc[nn][jj], ax2[nn], wr2);
            }
        }
    }

#pragma unroll
    for (int nn = 0; nn < 4; nn++) {
        int node = node0 + nn * 16 + ty;
        if (node < NN) {
#pragma unroll
            for (int jj = 0; jj < NJP; jj++) {
                float2 v = upk(acc[nn][jj]);
                v.x = fmaxf(v.x, 0.f); v.y = fmaxf(v.y, 0.f);
                *(float2*)&out[(size_t)node * DOUT + 2 * tx + 32 * jj] = v;
            }
        }
    }
}

// ========== single-input GEMM: pq[n][j] = hb@[Wl2|Wr2]^T + [0|b2], j=0..127 =========
__global__ void __launch_bounds__(256)
gemm_pq(const float* __restrict__ xin,
        const float* __restrict__ Wl,     // [64][96]
        const float* __restrict__ bias,   // [64]
        const float* __restrict__ Wr) {   // [64][96]
    constexpr int DOUT = 128;
    constexpr int WP = DOUT + 2;          // 130
    constexpr int NJP = 4;
    constexpr int AP = 2 * DIN + 4;       // 196
    extern __shared__ float sm[];
    float* Wt = sm;                       // [DIN][130]
    float* bs = Wt + DIN * WP;            // [128]
    float* A  = bs + DOUT;                // [64][196]

    int tid = threadIdx.x;
    for (int idx = tid; idx < 64 * DIN; idx += 256) {
        int j = idx / DIN, k = idx - j * DIN;
        Wt[k * WP + j]      = Wl[idx];
        Wt[k * WP + 64 + j] = Wr[idx];
    }
    if (tid < 128) bs[tid] = (tid < 64) ? 0.0f : bias[tid - 64];

    int node0 = blockIdx.x * 64;
    for (int idx = tid; idx < 64 * DIN; idx += 256) {
        int n = idx / DIN, k = idx - n * DIN;
        int node = node0 + n;
        float v = (node < NN) ? xin[(size_t)node * DIN + k] : 0.f;
        *(float2*)&A[n * AP + 2 * k] = make_float2(v, v);
    }
    __syncthreads();

    int tx = tid & 15, ty = tid >> 4;
    u64 acc[4][NJP];
#pragma unroll
    for (int jj = 0; jj < NJP; jj++) {
        float2 bp = *(const float2*)&bs[2 * tx + 32 * jj];
        u64 bv = pk(bp.x, bp.y);
#pragma unroll
        for (int nn = 0; nn < 4; nn++) acc[nn][jj] = bv;
    }

#pragma unroll 2
    for (int k = 0; k < DIN; k++) {
        u64 av[4];
#pragma unroll
        for (int nn = 0; nn < 4; nn++)
            av[nn] = *(const u64*)&A[(nn * 16 + ty) * AP + 2 * k];
#pragma unroll
        for (int jj = 0; jj < NJP; jj++) {
            u64 w2 = *(const u64*)&Wt[k * WP + 2 * tx + 32 * jj];
#pragma unroll
            for (int nn = 0; nn < 4; nn++)
                fma2(acc[nn][jj], av[nn], w2);
        }
    }

#pragma unroll
    for (int nn = 0; nn < 4; nn++) {
        int node = node0 + nn * 16 + ty;
        if (node < NN) {
#pragma unroll
            for (int jj = 0; jj < NJP; jj++) {
                float2 v = upk(acc[nn][jj]);
                *(float2*)&g_big[(size_t)node * 128 + 2 * tx + 32 * jj] = v;
            }
        }
    }
}

// ======== pool: block/graph; block finds its own bounds via binary search ========
__global__ void __launch_bounds__(256) pool_kernel(const float* __restrict__ h,
                                                   const int* __restrict__ batch,
                                                   float* __restrict__ out) {
    __shared__ float red[256];
    int g = blockIdx.x;
    int lo = 0, hi = NN;
    while (lo < hi) { int m = (lo + hi) >> 1; if (__ldg(&batch[m]) < g) lo = m + 1; else hi = m; }
    int beg = lo;
    hi = NN;
    while (lo < hi) { int m = (lo + hi) >> 1; if (__ldg(&batch[m]) < g + 1) lo = m + 1; else hi = m; }
    int end = lo;

    int col = threadIdx.x & 63, chunk = threadIdx.x >> 6;
    float s = 0.f;
    for (int n = beg + chunk; n < end; n += 4)
        s += h[(size_t)n * 64 + col];
    red[threadIdx.x] = s;
    __syncthreads();
    if (threadIdx.x < 64) {
        float v = red[threadIdx.x] + red[threadIdx.x + 64] +
                  red[threadIdx.x + 128] + red[threadIdx.x + 192];
        out[g * 64 + threadIdx.x] = v / fmaxf((float)(end - beg), 1.0f);
    }
}

extern "C" void kernel_launch(void* const* d_in, const int* in_sizes, int n_in,
                              void* d_out, int out_size) {
    const float* x     = (const float*)d_in[0];
    const int*   ei    = (const int*)d_in[1];
    const int*   batch = (const int*)d_in[2];
    const float* Wl0 = (const float*)d_in[3];
    const float* b0  = (const float*)d_in[4];
    const float* Wr0 = (const float*)d_in[5];
    const float* Wl1 = (const float*)d_in[6];
    const float* b1  = (const float*)d_in[7];
    const float* Wr1 = (const float*)d_in[8];
    const float* Wl2 = (const float*)d_in[9];
    const float* b2  = (const float*)d_in[10];
    const float* Wr2 = (const float*)d_in[11];
    float* out = (float*)d_out;

    const int* srcp = ei;
    const int* dstp = ei + NE;

    float *big, *ha, *hb;
    cudaGetSymbolAddress((void**)&big, g_big);
    cudaGetSymbolAddress((void**)&ha,  g_ha);
    cudaGetSymbolAddress((void**)&hb,  g_hb);

    const int SMEM96  = (2 * DIN * 98 + 96 + 64 * (4 * DIN + 4)) * (int)sizeof(float);
    const int SMEMPQ  = (DIN * 130 + 128 + 64 * (2 * DIN + 4)) * (int)sizeof(float);
    cudaFuncSetAttribute(sage_gemm<96>,
                         cudaFuncAttributeMaxDynamicSharedMemorySize, SMEM96);
    cudaFuncSetAttribute(gemm_pq,
                         cudaFuncAttributeMaxDynamicSharedMemorySize, SMEMPQ);

    const int T = 256;
    int gemm_grid = cdiv(NN, 64);
    int gather_grid = cdiv(NN * 32, T);

    // CSR build (g_cnt is zero on entry; scanall re-zeroes it)
    hist_kernel<<<cdiv(NE, T), T>>>(dstp);          // #1
    scanall_kernel<<<1, 1024>>>();                  // #2
    fill_kernel<<<cdiv(NE, T), T>>>(srcp, dstp);    // #3

    // layer 0: x -> ha   (g_big = mean aggregate)
    gather_kernel<<<gather_grid, T>>>(x);           // #4  (ncu profiles this)
    sage_gemm<96><<<gemm_grid, T, SMEM96>>>(x, big, Wl0, b0, Wr0, ha);   // #5

    // layer 1: ha -> hb
    gather_kernel<<<gather_grid, T>>>(ha);          // #6
    sage_gemm<96><<<gemm_grid, T, SMEM96>>>(ha, big, Wl1, b1, Wr1, hb);  // #7

    // layer 2 (project-then-gather): hb -> g_big(pq) -> ha[N,64]
    gemm_pq<<<gemm_grid, T, SMEMPQ>>>(hb, Wl2, b2, Wr2);                 // #8
    gather_pq_kernel<<<gather_grid, T>>>();         // #9

    // global mean pool
    pool_kernel<<<NG, 256>>>(ha, batch, out);       // #10
}

// round 13
// speedup vs baseline: 1.3273x; 1.3273x over previous
#include <cuda_runtime.h>

#define NN 50000
#define NE 800000
#define NG 128
#define DIN 96
#define SCAN_B 1024
#define NBLK ((NN + SCAN_B - 1) / SCAN_B)   // 49

// ---- scratch (__device__ globals; no allocs allowed) ----
// g_big: phase A (layers 0-1) mean-aggregate [NN*96]; phase B (layer 2) pq [NN*128]
__device__ float g_big[NN * 128];
__device__ float g_ha[NN * DIN];
__device__ float g_hb[NN * DIN];
__device__ int   g_cnt[NN];
__device__ int   g_excl[NBLK * SCAN_B];
__device__ int   g_bsum[64];
__device__ int   g_bsumx[64];
__device__ int   g_rowptr[NN + 1];
__device__ int   g_wp[NN];
__device__ int   g_esrc[NE];
__device__ int   g_bound[NG + 1];
__device__ float g_inv_cnt[NG];

static inline int cdiv(int a, int b) { return (a + b - 1) / b; }

// ---- f32x2 helpers (FFMA2 only reachable via PTX) ----
typedef unsigned long long u64;
__device__ __forceinline__ u64 pk(float lo, float hi) {
    u64 r; asm("mov.b64 %0,{%1,%2};" : "=l"(r) : "f"(lo), "f"(hi)); return r;
}
__device__ __forceinline__ float2 upk(u64 v) {
    float2 f; asm("mov.b64 {%0,%1},%2;" : "=f"(f.x), "=f"(f.y) : "l"(v)); return f;
}
__device__ __forceinline__ void fma2(u64& d, u64 a, u64 b) {
    asm("fma.rn.f32x2 %0,%1,%2,%0;" : "+l"(d) : "l"(a), "l"(b));
}

// ================= CSR build (parallel 3-kernel scan — round-4 proven) ============
__global__ void izero_kernel(int* __restrict__ p, int n) {
    int i = blockIdx.x * blockDim.x + threadIdx.x;
    if (i < n) p[i] = 0;
}

__global__ void hist_kernel(const int* __restrict__ dst) {
    int i = blockIdx.x * blockDim.x + threadIdx.x;
    if (i < NE) atomicAdd(&g_cnt[dst[i]], 1);
}

__global__ void __launch_bounds__(SCAN_B) scan1_kernel() {
    __shared__ int s[SCAN_B];
    int tid = threadIdx.x;
    int i = blockIdx.x * SCAN_B + tid;
    int v = (i < NN) ? g_cnt[i] : 0;
    s[tid] = v;
    __syncthreads();
    for (int off = 1; off < SCAN_B; off <<= 1) {
        int t = (tid >= off) ? s[tid - off] : 0;
        __syncthreads();
        s[tid] += t;
        __syncthreads();
    }
    g_excl[i] = s[tid] - v;
    if (tid == SCAN_B - 1) g_bsum[blockIdx.x] = s[tid];
}

__global__ void scan2_kernel() {
    __shared__ int s[64];
    int tid = threadIdx.x;
    int v = (tid < NBLK) ? g_bsum[tid] : 0;
    s[tid] = v;
    __syncthreads();
    for (int off = 1; off < 64; off <<= 1) {
        int t = (tid >= off) ? s[tid - off] : 0;
        __syncthreads();
        s[tid] += t;
        __syncthreads();
    }
    g_bsumx[tid] = s[tid] - v;
}

__global__ void scan3_kernel() {
    int i = blockIdx.x * blockDim.x + threadIdx.x;
    if (i < NN) {
        int rp = g_excl[i] + g_bsumx[i >> 10];
        g_rowptr[i] = rp;
        g_wp[i] = rp;
    } else if (i == NN) {
        g_rowptr[NN] = NE;
    }
}

__global__ void fill_kernel(const int* __restrict__ src, const int* __restrict__ dst) {
    int i = blockIdx.x * blockDim.x + threadIdx.x;
    if (i < NE) {
        int s = __ldg(&src[i]);
        int pos = atomicAdd(&g_wp[dst[i]], 1);
        g_esrc[pos] = s;
    }
}

__global__ void bounds_kernel(const int* __restrict__ batch) {
    __shared__ int b[NG + 1];
    int g = threadIdx.x;
    if (g <= NG) {
        int lo = 0, hi = NN;
        while (lo < hi) {
            int mid = (lo + hi) >> 1;
            if (batch[mid] < g) lo = mid + 1; else hi = mid;
        }
        g_bound[g] = lo;
        b[g] = lo;
    }
    __syncthreads();
    if (g < NG)
        g_inv_cnt[g] = 1.0f / fmaxf((float)(b[g + 1] - b[g]), 1.0f);
}

// ========== mean aggregation (96-wide): warp/node, shfl indices, float4 (round-4) ==
__global__ void __launch_bounds__(256) gather_kernel(const float* __restrict__ x) {
    int node = (blockIdx.x * blockDim.x + threadIdx.x) >> 5;
    int lane = threadIdx.x & 31;
    if (node >= NN) return;
    int beg = g_rowptr[node], end = g_rowptr[node + 1];

    float4 acc = make_float4(0.f, 0.f, 0.f, 0.f);
    const float4* __restrict__ x4 = (const float4*)x;   // row = 24 float4
    bool act = lane < 24;

    for (int base = beg; base < end; base += 32) {
        int cnt = end - base;
        if (cnt > 32) cnt = 32;
        int myidx = g_esrc[base + (lane < cnt ? lane : 0)];
        int j = 0;
        for (; j + 4 <= cnt; j += 4) {
            int s0 = __shfl_sync(0xffffffffu, myidx, j);
            int s1 = __shfl_sync(0xffffffffu, myidx, j + 1);
            int s2 = __shfl_sync(0xffffffffu, myidx, j + 2);
            int s3 = __shfl_sync(0xffffffffu, myidx, j + 3);
            if (act) {
                float4 v0 = __ldg(&x4[(size_t)s0 * 24 + lane]);
                float4 v1 = __ldg(&x4[(size_t)s1 * 24 + lane]);
                float4 v2 = __ldg(&x4[(size_t)s2 * 24 + lane]);
                float4 v3 = __ldg(&x4[(size_t)s3 * 24 + lane]);
                acc.x += (v0.x + v1.x) + (v2.x + v3.x);
                acc.y += (v0.y + v1.y) + (v2.y + v3.y);
                acc.z += (v0.z + v1.z) + (v2.z + v3.z);
                acc.w += (v0.w + v1.w) + (v2.w + v3.w);
            }
        }
        for (; j < cnt; j++) {
            int s0 = __shfl_sync(0xffffffffu, myidx, j);
            if (act) {
                float4 v0 = __ldg(&x4[(size_t)s0 * 24 + lane]);
                acc.x += v0.x; acc.y += v0.y; acc.z += v0.z; acc.w += v0.w;
            }
        }
    }
    if (act) {
        float inv = 1.0f / fmaxf((float)(end - beg), 1.0f);
        acc.x *= inv; acc.y *= inv; acc.z *= inv; acc.w *= inv;
        ((float4*)(g_big + (size_t)node * DIN))[lane] = acc;
    }
}

// ===== layer-2 gather: mean over p (cols 0..63 of pq) + q (cols 64..127) -> ha[N,64]
__global__ void __launch_bounds__(256) gather_pq_kernel() {
    int node = (blockIdx.x * blockDim.x + threadIdx.x) >> 5;
    int lane = threadIdx.x & 31;
    if (node >= NN) return;
    int beg = g_rowptr[node], end = g_rowptr[node + 1];

    const float2* __restrict__ pq2 = (const float2*)g_big;  // row = 64 float2
    float2 q = __ldg(&pq2[(size_t)node * 64 + 32 + lane]);
    float2 acc = make_float2(0.f, 0.f);

    for (int base = beg; base < end; base += 32) {
        int cnt = end - base;
        if (cnt > 32) cnt = 32;
        int myidx = g_esrc[base + (lane < cnt ? lane : 0)];
        int j = 0;
        for (; j + 4 <= cnt; j += 4) {
            int s0 = __shfl_sync(0xffffffffu, myidx, j);
            int s1 = __shfl_sync(0xffffffffu, myidx, j + 1);
            int s2 = __shfl_sync(0xffffffffu, myidx, j + 2);
            int s3 = __shfl_sync(0xffffffffu, myidx, j + 3);
            float2 v0 = __ldg(&pq2[(size_t)s0 * 64 + lane]);
            float2 v1 = __ldg(&pq2[(size_t)s1 * 64 + lane]);
            float2 v2 = __ldg(&pq2[(size_t)s2 * 64 + lane]);
            float2 v3 = __ldg(&pq2[(size_t)s3 * 64 + lane]);
            acc.x += (v0.x + v1.x) + (v2.x + v3.x);
            acc.y += (v0.y + v1.y) + (v2.y + v3.y);
        }
        for (; j < cnt; j++) {
            int s0 = __shfl_sync(0xffffffffu, myidx, j);
            float2 v0 = __ldg(&pq2[(size_t)s0 * 64 + lane]);
            acc.x += v0.x; acc.y += v0.y;
        }
    }
    float inv = 1.0f / fmaxf((float)(end - beg), 1.0f);
    float2 r = make_float2(acc.x * inv + q.x, acc.y * inv + q.y);
    ((float2*)(g_ha + (size_t)node * 64))[lane] = r;
}

// ================= dual-input SAGE GEMM (layers 0,1; f32x2, pre-dup A) ============
template<int DOUT>
__global__ void __launch_bounds__(256)
sage_gemm(const float* __restrict__ xin,
          const float* __restrict__ mean,
          const float* __restrict__ Wl,
          const float* __restrict__ bias,
          const float* __restrict__ Wr,
          float* __restrict__ out) {
    constexpr int WP  = DOUT + 2;
    constexpr int NJP = DOUT / 32;
    constexpr int AP  = 4 * DIN + 4;  // 388
    extern __shared__ float sm[];
    float* Wlt = sm;
    float* Wrt = Wlt + DIN * WP;
    float* bs  = Wrt + DIN * WP;
    float* A   = bs + DOUT;

    int tid = threadIdx.x;
    for (int idx = tid; idx < DOUT * DIN; idx += 256) {
        int j = idx / DIN, k = idx - j * DIN;
        Wlt[k * WP + j] = Wl[idx];
        Wrt[k * WP + j] = Wr[idx];
    }
    if (tid < DOUT) bs[tid] = bias[tid];

    int node0 = blockIdx.x * 64;
    for (int idx = tid; idx < 64 * DIN; idx += 256) {
        int n = idx / DIN, k = idx - n * DIN;
        int node = node0 + n;
        float m = 0.f, xv = 0.f;
        if (node < NN) {
            m  = mean[(size_t)node * DIN + k];
            xv = xin[(size_t)node * DIN + k];
        }
        *(float2*)&A[n * AP + 4 * k]     = make_float2(m, m);
        *(float2*)&A[n * AP + 4 * k + 2] = make_float2(xv, xv);
    }
    __syncthreads();

    int tx = tid & 15, ty = tid >> 4;
    u64 acc[4][NJP];
#pragma unroll
    for (int jj = 0; jj < NJP; jj++) {
        float2 bp = *(const float2*)&bs[2 * tx + 32 * jj];
        u64 bv = pk(bp.x, bp.y);
#pragma unroll
        for (int nn = 0; nn < 4; nn++) acc[nn][jj] = bv;
    }

#pragma unroll 2
    for (int k = 0; k < DIN; k++) {
        u64 am2[4], ax2[4];
#pragma unroll
        for (int nn = 0; nn < 4; nn++) {
            const float* ap = &A[(nn * 16 + ty) * AP + 4 * k];
            am2[nn] = *(const u64*)(ap);
            ax2[nn] = *(const u64*)(ap + 2);
        }
#pragma unroll
        for (int jj = 0; jj < NJP; jj++) {
            u64 wl2 = *(const u64*)&Wlt[k * WP + 2 * tx + 32 * jj];
            u64 wr2 = *(const u64*)&Wrt[k * WP + 2 * tx + 32 * jj];
#pragma unroll
            for (int nn = 0; nn < 4; nn++) {
                fma2(acc[nn][jj], am2[nn], wl2);
                fma2(acc[nn][jj], ax2[nn], wr2);
            }
        }
    }

#pragma unroll
    for (int nn = 0; nn < 4; nn++) {
        int node = node0 + nn * 16 + ty;
        if (node < NN) {
#pragma unroll
            for (int jj = 0; jj < NJP; jj++) {
                float2 v = upk(acc[nn][jj]);
                v.x = fmaxf(v.x, 0.f); v.y = fmaxf(v.y, 0.f);
                *(float2*)&out[(size_t)node * DOUT + 2 * tx + 32 * jj] = v;
            }
        }
    }
}

// ========== single-input GEMM: pq[n][j] = hb@[Wl2|Wr2]^T + [0|b2], j=0..127 =========
__global__ void __launch_bounds__(256)
gemm_pq(const float* __restrict__ xin,
        const float* __restrict__ Wl,     // [64][96]
        const float* __restrict__ bias,   // [64]
        const float* __restrict__ Wr) {   // [64][96]
    constexpr int DOUT = 128;
    constexpr int WP = DOUT + 2;          // 130
    constexpr int NJP = 4;
    constexpr int AP = 2 * DIN + 4;       // 196
    extern __shared__ float sm[];
    float* Wt = sm;                       // [DIN][130]
    float* bs = Wt + DIN * WP;            // [128]
    float* A  = bs + DOUT;                // [64][196]

    int tid = threadIdx.x;
    for (int idx = tid; idx < 64 * DIN; idx += 256) {
        int j = idx / DIN, k = idx - j * DIN;
        Wt[k * WP + j]      = Wl[idx];
        Wt[k * WP + 64 + j] = Wr[idx];
    }
    if (tid < 128) bs[tid] = (tid < 64) ? 0.0f : bias[tid - 64];

    int node0 = blockIdx.x * 64;
    for (int idx = tid; idx < 64 * DIN; idx += 256) {
        int n = idx / DIN, k = idx - n * DIN;
        int node = node0 + n;
        float v = (node < NN) ? xin[(size_t)node * DIN + k] : 0.f;
        *(float2*)&A[n * AP + 2 * k] = make_float2(v, v);
    }
    __syncthreads();

    int tx = tid & 15, ty = tid >> 4;
    u64 acc[4][NJP];
#pragma unroll
    for (int jj = 0; jj < NJP; jj++) {
        float2 bp = *(const float2*)&bs[2 * tx + 32 * jj];
        u64 bv = pk(bp.x, bp.y);
#pragma unroll
        for (int nn = 0; nn < 4; nn++) acc[nn][jj] = bv;
    }

#pragma unroll 2
    for (int k = 0; k < DIN; k++) {
        u64 av[4];
#pragma unroll
        for (int nn = 0; nn < 4; nn++)
            av[nn] = *(const u64*)&A[(nn * 16 + ty) * AP + 2 * k];
#pragma unroll
        for (int jj = 0; jj < NJP; jj++) {
            u64 w2 = *(const u64*)&Wt[k * WP + 2 * tx + 32 * jj];
#pragma unroll
            for (int nn = 0; nn < 4; nn++)
                fma2(acc[nn][jj], av[nn], w2);
        }
    }

#pragma unroll
    for (int nn = 0; nn < 4; nn++) {
        int node = node0 + nn * 16 + ty;
        if (node < NN) {
#pragma unroll
            for (int jj = 0; jj < NJP; jj++) {
                float2 v = upk(acc[nn][jj]);
                *(float2*)&g_big[(size_t)node * 128 + 2 * tx + 32 * jj] = v;
            }
        }
    }
}

// ================= pool: block per graph, precomputed bounds =================
__global__ void __launch_bounds__(256) pool_kernel(const float* __restrict__ h,
                                                   float* __restrict__ out) {
    __shared__ float red[256];
    int g = blockIdx.x;
    int beg = g_bound[g], end = g_bound[g + 1];
    int col = threadIdx.x & 63, chunk = threadIdx.x >> 6;
    float s = 0.f;
    for (int n = beg + chunk; n < end; n += 4)
        s += h[(size_t)n * 64 + col];
    red[threadIdx.x] = s;
    __syncthreads();
    if (threadIdx.x < 64) {
        float v = red[threadIdx.x] + red[threadIdx.x + 64] +
                  red[threadIdx.x + 128] + red[threadIdx.x + 192];
        out[g * 64 + threadIdx.x] = v * g_inv_cnt[g];
    }
}

extern "C" void kernel_launch(void* const* d_in, const int* in_sizes, int n_in,
                              void* d_out, int out_size) {
    const float* x     = (const float*)d_in[0];
    const int*   ei    = (const int*)d_in[1];
    const int*   batch = (const int*)d_in[2];
    const float* Wl0 = (const float*)d_in[3];
    const float* b0  = (const float*)d_in[4];
    const float* Wr0 = (const float*)d_in[5];
    const float* Wl1 = (const float*)d_in[6];
    const float* b1  = (const float*)d_in[7];
    const float* Wr1 = (const float*)d_in[8];
    const float* Wl2 = (const float*)d_in[9];
    const float* b2  = (const float*)d_in[10];
    const float* Wr2 = (const float*)d_in[11];
    float* out = (float*)d_out;

    const int* srcp = ei;
    const int* dstp = ei + NE;

    float *big, *ha, *hb;
    int* cnt;
    cudaGetSymbolAddress((void**)&big, g_big);
    cudaGetSymbolAddress((void**)&ha,  g_ha);
    cudaGetSymbolAddress((void**)&hb,  g_hb);
    cudaGetSymbolAddress((void**)&cnt, g_cnt);

    const int SMEM96 = (2 * DIN * 98 + 96 + 64 * (4 * DIN + 4)) * (int)sizeof(float);
    const int SMEMPQ = (DIN * 130 + 128 + 64 * (2 * DIN + 4)) * (int)sizeof(float);
    cudaFuncSetAttribute(sage_gemm<96>,
                         cudaFuncAttributeMaxDynamicSharedMemorySize, SMEM96);
    cudaFuncSetAttribute(gemm_pq,
                         cudaFuncAttributeMaxDynamicSharedMemorySize, SMEMPQ);

    const int T = 256;
    int gemm_grid = cdiv(NN, 64);
    int gather_grid = cdiv(NN * 32, T);

    // ---- CSR build (parallel scans) + graph bounds ----
    izero_kernel<<<cdiv(NN, T), T>>>(cnt, NN);
    hist_kernel<<<cdiv(NE, T), T>>>(dstp);
    scan1_kernel<<<NBLK, SCAN_B>>>();
    scan2_kernel<<<1, 64>>>();
    scan3_kernel<<<cdiv(NN + 1, T), T>>>();
    fill_kernel<<<cdiv(NE, T), T>>>(srcp, dstp);
    bounds_kernel<<<1, 256>>>(batch);

    // ---- layer 0: x -> ha  (g_big = mean aggregate) ----
    gather_kernel<<<gather_grid, T>>>(x);
    sage_gemm<96><<<gemm_grid, T, SMEM96>>>(x, big, Wl0, b0, Wr0, ha);

    // ---- layer 1: ha -> hb ----
    gather_kernel<<<gather_grid, T>>>(ha);
    sage_gemm<96><<<gemm_grid, T, SMEM96>>>(ha, big, Wl1, b1, Wr1, hb);

    // ---- layer 2 (project-then-gather): hb -> g_big(pq) -> ha[N,64] ----
    gemm_pq<<<gemm_grid, T, SMEMPQ>>>(hb, Wl2, b2, Wr2);
    gather_pq_kernel<<<gather_grid, T>>>();

    // ---- global mean pool ----
    pool_kernel<<<NG, 256>>>(ha, out);
}

// round 16
// speedup vs baseline: 1.3373x; 1.0075x over previous
#include <cuda_runtime.h>

#define NN 50000
#define NE 800000
#define NG 128
#define DIN 96
#define SCAN_B 1024
#define NBLK ((NN + SCAN_B - 1) / SCAN_B)   // 49

// ---- scratch (__device__ globals; no allocs allowed) ----
// g_big: phase A (layers 0-1) mean-aggregate [NN*96]; phase B (layer 2) pq [NN*128]
__device__ float g_big[NN * 128];
__device__ float g_ha[NN * DIN];
__device__ float g_hb[NN * DIN];
__device__ int   g_cnt[NN];      // INVARIANT: zero at entry (static init + scan1 re-zero)
__device__ int   g_excl[NBLK * SCAN_B];
__device__ int   g_bsum[64];
__device__ int   g_rowptr[NN + 1];
__device__ int   g_wp[NN];
__device__ int   g_esrc[NE];

static inline int cdiv(int a, int b) { return (a + b - 1) / b; }

// ---- f32x2 helpers (FFMA2 only reachable via PTX) ----
typedef unsigned long long u64;
__device__ __forceinline__ u64 pk(float lo, float hi) {
    u64 r; asm("mov.b64 %0,{%1,%2};" : "=l"(r) : "f"(lo), "f"(hi)); return r;
}
__device__ __forceinline__ float2 upk(u64 v) {
    float2 f; asm("mov.b64 {%0,%1},%2;" : "=f"(f.x), "=f"(f.y) : "l"(v)); return f;
}
__device__ __forceinline__ void fma2(u64& d, u64 a, u64 b) {
    asm("fma.rn.f32x2 %0,%1,%2,%0;" : "+l"(d) : "l"(a), "l"(b));
}

// ================= CSR build =================
__global__ void hist_kernel(const int* __restrict__ dst) {
    int i = blockIdx.x * blockDim.x + threadIdx.x;
    if (i < NE) atomicAdd(&g_cnt[dst[i]], 1);
}

// block-level scan; also re-zeroes g_cnt (maintains entry invariant, replaces izero)
__global__ void __launch_bounds__(SCAN_B) scan1_kernel() {
    __shared__ int s[SCAN_B];
    int tid = threadIdx.x;
    int i = blockIdx.x * SCAN_B + tid;
    int v = 0;
    if (i < NN) { v = g_cnt[i]; g_cnt[i] = 0; }
    s[tid] = v;
    __syncthreads();
    for (int off = 1; off < SCAN_B; off <<= 1) {
        int t = (tid >= off) ? s[tid - off] : 0;
        __syncthreads();
        s[tid] += t;
        __syncthreads();
    }
    g_excl[i] = s[tid] - v;
    if (tid == SCAN_B - 1) g_bsum[blockIdx.x] = s[tid];
}

// merged scan2+scan3: every block redundantly scans the 49 block sums (trivial),
// then writes rowptr/wp for its 256 nodes.
__global__ void __launch_bounds__(256) scan23_kernel() {
    __shared__ int bx[64];
    __shared__ int exc[64];
    int tid = threadIdx.x;
    int v = 0;
    if (tid < 64) { v = (tid < NBLK) ? g_bsum[tid] : 0; bx[tid] = v; }
    __syncthreads();
    for (int off = 1; off < 64; off <<= 1) {
        int t = 0;
        if (tid >= off && tid < 64) t = bx[tid - off];
        __syncthreads();
        if (tid < 64) bx[tid] += t;
        __syncthreads();
    }
    if (tid < 64) exc[tid] = bx[tid] - v;
    __syncthreads();
    int i = blockIdx.x * blockDim.x + tid;
    if (i < NN) {
        int rp = g_excl[i] + exc[i >> 10];
        g_rowptr[i] = rp;
        g_wp[i] = rp;
    } else if (i == NN) {
        g_rowptr[NN] = NE;
    }
}

__global__ void fill_kernel(const int* __restrict__ src, const int* __restrict__ dst) {
    int i = blockIdx.x * blockDim.x + threadIdx.x;
    if (i < NE) {
        int s = __ldg(&src[i]);
        int pos = atomicAdd(&g_wp[dst[i]], 1);
        g_esrc[pos] = s;
    }
}

// ========== mean aggregation (96-wide): warp/node, shfl indices, float4 ==========
__global__ void __launch_bounds__(256) gather_kernel(const float* __restrict__ x) {
    int node = (blockIdx.x * blockDim.x + threadIdx.x) >> 5;
    int lane = threadIdx.x & 31;
    if (node >= NN) return;
    int beg = g_rowptr[node], end = g_rowptr[node + 1];

    float4 acc = make_float4(0.f, 0.f, 0.f, 0.f);
    const float4* __restrict__ x4 = (const float4*)x;   // row = 24 float4
    bool act = lane < 24;

    for (int base = beg; base < end; base += 32) {
        int cnt = end - base;
        if (cnt > 32) cnt = 32;
        int myidx = g_esrc[base + (lane < cnt ? lane : 0)];
        int j = 0;
        for (; j + 4 <= cnt; j += 4) {
            int s0 = __shfl_sync(0xffffffffu, myidx, j);
            int s1 = __shfl_sync(0xffffffffu, myidx, j + 1);
            int s2 = __shfl_sync(0xffffffffu, myidx, j + 2);
            int s3 = __shfl_sync(0xffffffffu, myidx, j + 3);
            if (act) {
                float4 v0 = __ldg(&x4[(size_t)s0 * 24 + lane]);
                float4 v1 = __ldg(&x4[(size_t)s1 * 24 + lane]);
                float4 v2 = __ldg(&x4[(size_t)s2 * 24 + lane]);
                float4 v3 = __ldg(&x4[(size_t)s3 * 24 + lane]);
                acc.x += (v0.x + v1.x) + (v2.x + v3.x);
                acc.y += (v0.y + v1.y) + (v2.y + v3.y);
                acc.z += (v0.z + v1.z) + (v2.z + v3.z);
                acc.w += (v0.w + v1.w) + (v2.w + v3.w);
            }
        }
        for (; j < cnt; j++) {
            int s0 = __shfl_sync(0xffffffffu, myidx, j);
            if (act) {
                float4 v0 = __ldg(&x4[(size_t)s0 * 24 + lane]);
                acc.x += v0.x; acc.y += v0.y; acc.z += v0.z; acc.w += v0.w;
            }
        }
    }
    if (act) {
        float inv = 1.0f / fmaxf((float)(end - beg), 1.0f);
        acc.x *= inv; acc.y *= inv; acc.z *= inv; acc.w *= inv;
        ((float4*)(g_big + (size_t)node * DIN))[lane] = acc;
    }
}

// ===== layer-2 gather: mean over p (cols 0..63 of pq) + q (cols 64..127) -> ha[N,64]
__global__ void __launch_bounds__(256) gather_pq_kernel() {
    int node = (blockIdx.x * blockDim.x + threadIdx.x) >> 5;
    int lane = threadIdx.x & 31;
    if (node >= NN) return;
    int beg = g_rowptr[node], end = g_rowptr[node + 1];

    const float2* __restrict__ pq2 = (const float2*)g_big;  // row = 64 float2
    float2 q = __ldg(&pq2[(size_t)node * 64 + 32 + lane]);
    float2 acc = make_float2(0.f, 0.f);

    for (int base = beg; base < end; base += 32) {
        int cnt = end - base;
        if (cnt > 32) cnt = 32;
        int myidx = g_esrc[base + (lane < cnt ? lane : 0)];
        int j = 0;
        for (; j + 4 <= cnt; j += 4) {
            int s0 = __shfl_sync(0xffffffffu, myidx, j);
            int s1 = __shfl_sync(0xffffffffu, myidx, j + 1);
            int s2 = __shfl_sync(0xffffffffu, myidx, j + 2);
            int s3 = __shfl_sync(0xffffffffu, myidx, j + 3);
            float2 v0 = __ldg(&pq2[(size_t)s0 * 64 + lane]);
            float2 v1 = __ldg(&pq2[(size_t)s1 * 64 + lane]);
            float2 v2 = __ldg(&pq2[(size_t)s2 * 64 + lane]);
            float2 v3 = __ldg(&pq2[(size_t)s3 * 64 + lane]);
            acc.x += (v0.x + v1.x) + (v2.x + v3.x);
            acc.y += (v0.y + v1.y) + (v2.y + v3.y);
        }
        for (; j < cnt; j++) {
            int s0 = __shfl_sync(0xffffffffu, myidx, j);
            float2 v0 = __ldg(&pq2[(size_t)s0 * 64 + lane]);
            acc.x += v0.x; acc.y += v0.y;
        }
    }
    float inv = 1.0f / fmaxf((float)(end - beg), 1.0f);
    float2 r = make_float2(acc.x * inv + q.x, acc.y * inv + q.y);
    ((float2*)(g_ha + (size_t)node * 64))[lane] = r;
}

// ============ dual-input SAGE GEMM (layers 0,1): all-LDS.128 inner loop ============
// A[n] float4-per-k = {m,m,x,x} (8 floats per k2); weights packed double-k:
//   Wp4[k2][p] = {W[2k2][2p], W[2k2][2p+1], W[2k2+1][2p], W[2k2+1][2p+1]}
template<int DOUT>
__global__ void __launch_bounds__(256)
sage_gemm(const float* __restrict__ xin,
          const float* __restrict__ mean,
          const float* __restrict__ Wl,
          const float* __restrict__ bias,
          const float* __restrict__ Wr,
          float* __restrict__ out) {
    constexpr int NJP = DOUT / 32;        // 3
    constexpr int P4  = DOUT / 2 + 1;     // 49 float4 per k2 row
    constexpr int K2  = DIN / 2;          // 48
    constexpr int WF  = K2 * P4 * 4;      // 9408 floats per packed weight matrix
    constexpr int AP  = 4 * DIN + 4;      // 388 floats per A row
    extern __shared__ float sm[];
    float* Wlp = sm;                      // [K2][P4] float4
    float* Wrp = Wlp + WF;
    float* bs  = Wrp + WF;                // [DOUT]
    float* A   = bs + DOUT;               // [64][AP], base 16B-aligned

    int tid = threadIdx.x;
    for (int idx = tid; idx < DOUT * DIN; idx += 256) {
        int j = idx / DIN, k = idx - j * DIN;
        int off = ((k >> 1) * P4 + (j >> 1)) * 4 + (k & 1) * 2 + (j & 1);
        Wlp[off] = Wl[idx];
        Wrp[off] = Wr[idx];
    }
    if (tid < DOUT) bs[tid] = bias[tid];

    int node0 = blockIdx.x * 64;
    for (int idx = tid; idx < 64 * DIN; idx += 256) {
        int n = idx / DIN, k = idx - n * DIN;
        int node = node0 + n;
        float m = 0.f, xv = 0.f;
        if (node < NN) {
            m  = mean[(size_t)node * DIN + k];
            xv = xin[(size_t)node * DIN + k];
        }
        *(float4*)&A[n * AP + 4 * k] = make_float4(m, m, xv, xv);
    }
    __syncthreads();

    int tx = tid & 15, ty = tid >> 4;
    u64 acc[4][NJP];
#pragma unroll
    for (int jj = 0; jj < NJP; jj++) {
        float2 bp = *(const float2*)&bs[2 * tx + 32 * jj];
        u64 bv = pk(bp.x, bp.y);
#pragma unroll
        for (int nn = 0; nn < 4; nn++) acc[nn][jj] = bv;
    }

    const ulonglong2* __restrict__ Wl4 = (const ulonglong2*)Wlp;
    const ulonglong2* __restrict__ Wr4 = (const ulonglong2*)Wrp;

#pragma unroll 2
    for (int k2 = 0; k2 < K2; k2++) {
        ulonglong2 a0[4], a1[4];   // .x={m,m} .y={x,x} for k=2k2 and 2k2+1
#pragma unroll
        for (int nn = 0; nn < 4; nn++) {
            const float* ap = &A[(nn * 16 + ty) * AP + 8 * k2];   // 8 floats per k2
            a0[nn] = *(const ulonglong2*)(ap);
            a1[nn] = *(const ulonglong2*)(ap + 4);
        }
#pragma unroll
        for (int jj = 0; jj < NJP; jj++) {
            ulonglong2 wl = Wl4[k2 * P4 + jj * 16 + tx];   // .x = k even, .y = k odd
            ulonglong2 wr = Wr4[k2 * P4 + jj * 16 + tx];
#pragma unroll
            for (int nn = 0; nn < 4; nn++) {
                fma2(acc[nn][jj], a0[nn].x, wl.x);
                fma2(acc[nn][jj], a0[nn].y, wr.x);
                fma2(acc[nn][jj], a1[nn].x, wl.y);
                fma2(acc[nn][jj], a1[nn].y, wr.y);
            }
        }
    }

#pragma unroll
    for (int nn = 0; nn < 4; nn++) {
        int node = node0 + nn * 16 + ty;
        if (node < NN) {
#pragma unroll
            for (int jj = 0; jj < NJP; jj++) {
                float2 v = upk(acc[nn][jj]);
                v.x = fmaxf(v.x, 0.f); v.y = fmaxf(v.y, 0.f);
                *(float2*)&out[(size_t)node * DOUT + 2 * tx + 32 * jj] = v;
            }
        }
    }
}

// ====== single-input GEMM: pq[n][j] = hb@[Wl2|Wr2]^T + [0|b2], j=0..127 ======
// A[n] packs 4 floats per k2: {v_even,v_even,v_odd,v_odd}
__global__ void __launch_bounds__(256)
gemm_pq(const float* __restrict__ xin,
        const float* __restrict__ Wl,     // [64][96]
        const float* __restrict__ bias,   // [64]
        const float* __restrict__ Wr) {   // [64][96]
    constexpr int DOUT = 128;
    constexpr int NJP = 4;
    constexpr int P4  = DOUT / 2 + 1;     // 65
    constexpr int K2  = DIN / 2;          // 48
    constexpr int WF  = K2 * P4 * 4;      // 12480 floats
    constexpr int AP  = K2 * 4;           // 196 floats per A row (4 per k2)
    extern __shared__ float sm[];
    float* Wp = sm;                       // [K2][P4] float4 (combined Wl|Wr)
    float* bs = Wp + WF;                  // [128]
    float* A  = bs + DOUT;                // [64][196], base 16B-aligned

    int tid = threadIdx.x;
    for (int idx = tid; idx < 64 * DIN; idx += 256) {
        int j = idx / DIN, k = idx - j * DIN;
        int offl = ((k >> 1) * P4 + (j >> 1)) * 4 + (k & 1) * 2 + (j & 1);
        int jr = j + 64;
        int offr = ((k >> 1) * P4 + (jr >> 1)) * 4 + (k & 1) * 2 + (jr & 1);
        Wp[offl] = Wl[idx];
        Wp[offr] = Wr[idx];
    }
    if (tid < 128) bs[tid] = (tid < 64) ? 0.0f : bias[tid - 64];

    int node0 = blockIdx.x * 64;
    for (int idx = tid; idx < 64 * DIN; idx += 256) {
        int n = idx / DIN, k = idx - n * DIN;
        int node = node0 + n;
        float v = (node < NN) ? xin[(size_t)node * DIN + k] : 0.f;
        int base = n * AP + (k >> 1) * 4 + (k & 1) * 2;
        A[base] = v; A[base + 1] = v;
    }
    __syncthreads();

    int tx = tid & 15, ty = tid >> 4;
    u64 acc[4][NJP];
#pragma unroll
    for (int jj = 0; jj < NJP; jj++) {
        float2 bp = *(const float2*)&bs[2 * tx + 32 * jj];
        u64 bv = pk(bp.x, bp.y);
#pragma unroll
        for (int nn = 0; nn < 4; nn++) acc[nn][jj] = bv;
    }

    const ulonglong2* __restrict__ W4 = (const ulonglong2*)Wp;

#pragma unroll 2
    for (int k2 = 0; k2 < K2; k2++) {
        ulonglong2 a[4];   // .x = {v,v} k even, .y = {v,v} k odd
#pragma unroll
        for (int nn = 0; nn < 4; nn++)
            a[nn] = *(const ulonglong2*)&A[(nn * 16 + ty) * AP + 4 * k2];
#pragma unroll
        for (int jj = 0; jj < NJP; jj++) {
            ulonglong2 w = W4[k2 * P4 + jj * 16 + tx];
#pragma unroll
            for (int nn = 0; nn < 4; nn++) {
                fma2(acc[nn][jj], a[nn].x, w.x);
                fma2(acc[nn][jj], a[nn].y, w.y);
            }
        }
    }

#pragma unroll
    for (int nn = 0; nn < 4; nn++) {
        int node = node0 + nn * 16 + ty;
        if (node < NN) {
#pragma unroll
            for (int jj = 0; jj < NJP; jj++) {
                float2 v = upk(acc[nn][jj]);
                *(float2*)&g_big[(size_t)node * 128 + 2 * tx + 32 * jj] = v;
            }
        }
    }
}

// ======== pool: block/graph; bounds via in-block binary search ========
__global__ void __launch_bounds__(256) pool_kernel(const float* __restrict__ h,
                                                   const int* __restrict__ batch,
                                                   float* __restrict__ out) {
    __shared__ float red[256];
    int g = blockIdx.x;
    int lo = 0, hi = NN;
    while (lo < hi) { int m = (lo + hi) >> 1; if (__ldg(&batch[m]) < g) lo = m + 1; else hi = m; }
    int beg = lo;
    hi = NN;
    while (lo < hi) { int m = (lo + hi) >> 1; if (__ldg(&batch[m]) < g + 1) lo = m + 1; else hi = m; }
    int end = lo;

    int col = threadIdx.x & 63, chunk = threadIdx.x >> 6;
    float s = 0.f;
    for (int n = beg + chunk; n < end; n += 4)
        s += h[(size_t)n * 64 + col];
    red[threadIdx.x] = s;
    __syncthreads();
    if (threadIdx.x < 64) {
        float v = red[threadIdx.x] + red[threadIdx.x + 64] +
                  red[threadIdx.x + 128] + red[threadIdx.x + 192];
        out[g * 64 + threadIdx.x] = v / fmaxf((float)(end - beg), 1.0f);
    }
}

extern "C" void kernel_launch(void* const* d_in, const int* in_sizes, int n_in,
                              void* d_out, int out_size) {
    const float* x     = (const float*)d_in[0];
    const int*   ei    = (const int*)d_in[1];
    const int*   batch = (const int*)d_in[2];
    const float* Wl0 = (const float*)d_in[3];
    const float* b0  = (const float*)d_in[4];
    const float* Wr0 = (const float*)d_in[5];
    const float* Wl1 = (const float*)d_in[6];
    const float* b1  = (const float*)d_in[7];
    const float* Wr1 = (const float*)d_in[8];
    const float* Wl2 = (const float*)d_in[9];
    const float* b2  = (const float*)d_in[10];
    const float* Wr2 = (const float*)d_in[11];
    float* out = (float*)d_out;

    const int* srcp = ei;
    const int* dstp = ei + NE;

    float *big, *ha, *hb;
    cudaGetSymbolAddress((void**)&big, g_big);
    cudaGetSymbolAddress((void**)&ha,  g_ha);
    cudaGetSymbolAddress((void**)&hb,  g_hb);

    const int SMEM96 = (2 * (DIN / 2) * (96 / 2 + 1) * 4 + 96 + 64 * (4 * DIN + 4)) * (int)sizeof(float);
    const int SMEMPQ = ((DIN / 2) * 65 * 4 + 128 + 64 * ((DIN / 2) * 4)) * (int)sizeof(float);
    cudaFuncSetAttribute(sage_gemm<96>,
                         cudaFuncAttributeMaxDynamicSharedMemorySize, SMEM96);
    cudaFuncSetAttribute(gemm_pq,
                         cudaFuncAttributeMaxDynamicSharedMemorySize, SMEMPQ);

    const int T = 256;
    int gemm_grid = cdiv(NN, 64);
    int gather_grid = cdiv(NN * 32, T);

    // ---- CSR build (g_cnt zero on entry; scan1 re-zeroes) ----
    hist_kernel<<<cdiv(NE, T), T>>>(dstp);              // #1
    scan1_kernel<<<NBLK, SCAN_B>>>();                   // #2
    scan23_kernel<<<cdiv(NN + 1, T), T>>>();            // #3
    fill_kernel<<<cdiv(NE, T), T>>>(srcp, dstp);        // #4

    // ---- layer 0: x -> ha  (g_big = mean aggregate) ----
    gather_kernel<<<gather_grid, T>>>(x);               // #5
    sage_gemm<96><<<gemm_grid, T, SMEM96>>>(x, big, Wl0, b0, Wr0, ha);   // #6

    // ---- layer 1: ha -> hb ----
    gather_kernel<<<gather_grid, T>>>(ha);              // #7
    sage_gemm<96><<<gemm_grid, T, SMEM96>>>(ha, big, Wl1, b1, Wr1, hb);  // #8

    // ---- layer 2 (project-then-gather): hb -> g_big(pq) -> ha[N,64] ----
    gemm_pq<<<gemm_grid, T, SMEMPQ>>>(hb, Wl2, b2, Wr2);                 // #9
    gather_pq_kernel<<<gather_grid, T>>>();             // #10

    // ---- global mean pool ----
    pool_kernel<<<NG, 256>>>(ha, batch, out);           // #11
}